// round 1
// baseline (speedup 1.0000x reference)
#include <cuda_runtime.h>
#include <cstdint>
#include <cstddef>

// ---------------------------------------------------------------------------
// LoRALinear: out = X @ dequant_nf4(Wq,scales)^T + (alpha/r) * (X @ A^T) @ B^T
// Strategy: fold LoRA into the dequantized weight once per launch, then run a
// single tf32 mma.sync GEMM (M=8192, N=4096, K=4096) with fp32 accumulation.
// ---------------------------------------------------------------------------

#define IN_DIM   4096
#define OUT_DIM  4096
#define RANK_    16
#define M_MAX    8192

__constant__ float c_nf4[16] = {
    -1.0f, -0.6961928009986877f, -0.5250730514526367f, -0.39491748809814453f,
    -0.28444138169288635f, -0.18477343022823334f, -0.09105003625154495f, 0.0f,
    0.07958029955625534f, 0.16093020141124725f, 0.24611230194568634f,
    0.33791524171829224f, 0.44070982933044434f, 0.5626170039176941f,
    0.7229568362236023f, 1.0f };

// Scratch (allocation-free rule: device globals)
__device__ float g_w[(size_t)OUT_DIM * IN_DIM];   // dequant + LoRA folded, tf32-rounded
__device__ float g_x[(size_t)M_MAX * IN_DIM];     // tf32-rounded activations

__device__ __forceinline__ unsigned tf32_rna(float x) {
    unsigned u;
    asm("cvt.rna.tf32.f32 %0, %1;" : "=r"(u) : "f"(x));
    return u;
}

// ---------------------------------------------------------------------------
// Kernel 1: round X to tf32 (zero-mean rounding; avoids MMA truncation bias)
// ---------------------------------------------------------------------------
__global__ void round_x_kernel(const float* __restrict__ x, float* __restrict__ xr, int n4) {
    int i = blockIdx.x * blockDim.x + threadIdx.x;
    if (i >= n4) return;
    float4 v = reinterpret_cast<const float4*>(x)[i];
    uint4 u;
    u.x = tf32_rna(v.x); u.y = tf32_rna(v.y);
    u.z = tf32_rna(v.z); u.w = tf32_rna(v.w);
    reinterpret_cast<uint4*>(xr)[i] = u;
}

// ---------------------------------------------------------------------------
// Kernel 2: W'[o,i] = nf4[wq[o,i]] * scales[o, i/64] + 2 * sum_r B[o,r]*A[r,i]
// tf32-rounded. One float4 of W' per thread.
// ---------------------------------------------------------------------------
__global__ void dequant_fold_kernel(const int* __restrict__ wq,
                                    const float* __restrict__ scales,
                                    const float* __restrict__ la,   // [16, 4096]
                                    const float* __restrict__ lb,   // [4096, 16]
                                    float* __restrict__ W) {
    __shared__ float cb[16];
    if (threadIdx.x < 16) cb[threadIdx.x] = c_nf4[threadIdx.x];
    __syncthreads();

    int idx = blockIdx.x * blockDim.x + threadIdx.x;       // one float4
    const int n4 = OUT_DIM * (IN_DIM / 4);
    if (idx >= n4) return;
    int o  = idx >> 10;              // IN_DIM/4 = 1024 float4 per row
    int i4 = idx & 1023;

    int4 c = reinterpret_cast<const int4*>(wq)[idx];
    float s = scales[o * (IN_DIM / 64) + (i4 >> 4)];        // block of 64 = 16 float4

    // rank-16 LoRA fold (alpha/rank = 2.0)
    float lx = 0.f, ly = 0.f, lz = 0.f, lw = 0.f;
    #pragma unroll
    for (int r = 0; r < RANK_; r++) {
        float bb = __ldg(&lb[o * RANK_ + r]);
        float4 av = reinterpret_cast<const float4*>(la)[r * (IN_DIM / 4) + i4];
        lx = fmaf(bb, av.x, lx); ly = fmaf(bb, av.y, ly);
        lz = fmaf(bb, av.z, lz); lw = fmaf(bb, av.w, lw);
    }

    float4 wv;
    wv.x = fmaf(cb[c.x], s, 2.0f * lx);
    wv.y = fmaf(cb[c.y], s, 2.0f * ly);
    wv.z = fmaf(cb[c.z], s, 2.0f * lz);
    wv.w = fmaf(cb[c.w], s, 2.0f * lw);

    uint4 u;
    u.x = tf32_rna(wv.x); u.y = tf32_rna(wv.y);
    u.z = tf32_rna(wv.z); u.w = tf32_rna(wv.w);
    reinterpret_cast<uint4*>(W)[idx] = u;
}

// ---------------------------------------------------------------------------
// Kernel 3: tf32 GEMM  C[M,N] = A[M,K] @ B[N,K]^T   (both K-major, fp32 accum)
// 128x128x32 tiles, 256 threads (8 warps, 2x4), cp.async double buffer.
// ---------------------------------------------------------------------------
#define BM 128
#define BN 128
#define BK 32
#define LDS_W 36            // BK + 4 floats pad (keeps 16B alignment, kills conflicts)

__device__ __forceinline__ unsigned smem_u32(const void* p) {
    return (unsigned)__cvta_generic_to_shared(p);
}

__global__ void __launch_bounds__(256)
gemm_tf32_kernel(const float* __restrict__ A, const float* __restrict__ B,
                 float* __restrict__ C, int M, int N, int K) {
    extern __shared__ float sm[];
    float* As = sm;                       // 2 * BM * LDS_W
    float* Bs = sm + 2 * BM * LDS_W;      // 2 * BN * LDS_W

    const int tid  = threadIdx.x;
    const int lane = tid & 31;
    const int w    = tid >> 5;
    const int wm   = (w & 1) * 64;        // warp tile: 64(M) x 32(N)
    const int wn   = (w >> 1) * 32;
    const int g    = lane >> 2;           // groupID
    const int tg   = lane & 3;            // threadID in group

    const int lrow = tid >> 3;            // 0..31
    const int lcol = (tid & 7) * 4;       // 0..28 step 4

    const float* Ag = A + (size_t)(blockIdx.y * BM + lrow) * K + lcol;
    const float* Bg = B + (size_t)(blockIdx.x * BN + lrow) * K + lcol;

    float acc[4][4][4];
    #pragma unroll
    for (int a = 0; a < 4; a++)
        #pragma unroll
        for (int b = 0; b < 4; b++)
            #pragma unroll
            for (int c = 0; c < 4; c++) acc[a][b][c] = 0.f;

    const int KT = K / BK;

    // async load of one stage
    auto load_stage = [&](int buf, int kt) {
        unsigned abase = smem_u32(As + buf * BM * LDS_W);
        unsigned bbase = smem_u32(Bs + buf * BN * LDS_W);
        const float* asrc = Ag + (size_t)kt * BK;
        const float* bsrc = Bg + (size_t)kt * BK;
        #pragma unroll
        for (int p = 0; p < 4; p++) {
            unsigned ad = abase + (unsigned)(((lrow + p * 32) * LDS_W + lcol) * 4);
            unsigned bd = bbase + (unsigned)(((lrow + p * 32) * LDS_W + lcol) * 4);
            asm volatile("cp.async.cg.shared.global [%0], [%1], 16;\n"
                         :: "r"(ad), "l"(asrc + (size_t)p * 32 * K));
            asm volatile("cp.async.cg.shared.global [%0], [%1], 16;\n"
                         :: "r"(bd), "l"(bsrc + (size_t)p * 32 * K));
        }
    };

    load_stage(0, 0);
    asm volatile("cp.async.commit_group;\n");
    load_stage(1, 1);
    asm volatile("cp.async.commit_group;\n");

    for (int kt = 0; kt < KT; kt++) {
        asm volatile("cp.async.wait_group 1;\n");
        __syncthreads();

        const float* as = As + (kt & 1) * BM * LDS_W;
        const float* bs = Bs + (kt & 1) * BN * LDS_W;

        #pragma unroll
        for (int s = 0; s < 4; s++) {
            unsigned af[4][4], bf[4][2];
            #pragma unroll
            for (int mi = 0; mi < 4; mi++) {
                const float* p = as + (wm + mi * 16 + g) * LDS_W + s * 8 + tg;
                af[mi][0] = __float_as_uint(p[0]);
                af[mi][1] = __float_as_uint(p[8 * LDS_W]);
                af[mi][2] = __float_as_uint(p[4]);
                af[mi][3] = __float_as_uint(p[8 * LDS_W + 4]);
            }
            #pragma unroll
            for (int ni = 0; ni < 4; ni++) {
                const float* p = bs + (wn + ni * 8 + g) * LDS_W + s * 8 + tg;
                bf[ni][0] = __float_as_uint(p[0]);
                bf[ni][1] = __float_as_uint(p[4]);
            }
            #pragma unroll
            for (int mi = 0; mi < 4; mi++)
                #pragma unroll
                for (int ni = 0; ni < 4; ni++) {
                    asm volatile(
                        "mma.sync.aligned.m16n8k8.row.col.f32.tf32.tf32.f32 "
                        "{%0,%1,%2,%3}, {%4,%5,%6,%7}, {%8,%9}, {%0,%1,%2,%3};\n"
                        : "+f"(acc[mi][ni][0]), "+f"(acc[mi][ni][1]),
                          "+f"(acc[mi][ni][2]), "+f"(acc[mi][ni][3])
                        : "r"(af[mi][0]), "r"(af[mi][1]), "r"(af[mi][2]), "r"(af[mi][3]),
                          "r"(bf[ni][0]), "r"(bf[ni][1]));
                }
        }

        __syncthreads();
        if (kt + 2 < KT) load_stage(kt & 1, kt + 2);
        asm volatile("cp.async.commit_group;\n");   // empty group OK near the tail
    }

    // epilogue: direct fp32 stores (float2 per c-pair)
    #pragma unroll
    for (int mi = 0; mi < 4; mi++) {
        int row0 = blockIdx.y * BM + wm + mi * 16 + g;
        #pragma unroll
        for (int ni = 0; ni < 4; ni++) {
            int col = blockIdx.x * BN + wn + ni * 8 + tg * 2;
            float2 v0 = make_float2(acc[mi][ni][0], acc[mi][ni][1]);
            float2 v1 = make_float2(acc[mi][ni][2], acc[mi][ni][3]);
            *reinterpret_cast<float2*>(&C[(size_t)row0 * N + col])       = v0;
            *reinterpret_cast<float2*>(&C[(size_t)(row0 + 8) * N + col]) = v1;
        }
    }
}

// ---------------------------------------------------------------------------
// Launcher
// ---------------------------------------------------------------------------
extern "C" void kernel_launch(void* const* d_in, const int* in_sizes, int n_in,
                              void* d_out, int out_size) {
    const float* x      = (const float*)d_in[0];
    const int*   wq     = (const int*)  d_in[1];
    const float* scales = (const float*)d_in[2];
    const float* la     = (const float*)d_in[3];
    const float* lb     = (const float*)d_in[4];
    float* out = (float*)d_out;

    int M = in_sizes[0] / IN_DIM;    // 8192

    float *gw = nullptr, *gx = nullptr;
    cudaGetSymbolAddress((void**)&gw, g_w);
    cudaGetSymbolAddress((void**)&gx, g_x);

    // 1) tf32-round X
    int n4x = (M * IN_DIM) / 4;
    round_x_kernel<<<(n4x + 255) / 256, 256>>>(x, gx, n4x);

    // 2) dequant + LoRA fold into W'
    int n4w = OUT_DIM * (IN_DIM / 4);
    dequant_fold_kernel<<<(n4w + 255) / 256, 256>>>(wq, scales, la, lb, gw);

    // 3) GEMM
    const int smem_bytes = 2 * (BM * LDS_W + BN * LDS_W) * (int)sizeof(float); // 73728
    cudaFuncSetAttribute(gemm_tf32_kernel,
                         cudaFuncAttributeMaxDynamicSharedMemorySize, smem_bytes);
    dim3 grid(OUT_DIM / BN, M / BM);   // (32, 64)
    gemm_tf32_kernel<<<grid, 256, smem_bytes>>>(gx, gw, out, M, OUT_DIM, IN_DIM);
}

// round 3
// speedup vs baseline: 1.0322x; 1.0322x over previous
#include <cuda_runtime.h>
#include <cstdint>
#include <cstddef>

// ---------------------------------------------------------------------------
// LoRALinear: fold NF4-dequant + LoRA into W' (tf32-rounded), then a tf32
// mma.sync GEMM (M=8192, N=4096, K=4096), 128x256 CTA tile, 3-stage cp.async.
// (tcgen05 unavailable: harness compiles via compute_103 virtual arch.)
// ---------------------------------------------------------------------------

#define IN_DIM   4096
#define OUT_DIM  4096
#define RANK_    16
#define M_MAX    8192

__constant__ float c_nf4[16] = {
    -1.0f, -0.6961928009986877f, -0.5250730514526367f, -0.39491748809814453f,
    -0.28444138169288635f, -0.18477343022823334f, -0.09105003625154495f, 0.0f,
    0.07958029955625534f, 0.16093020141124725f, 0.24611230194568634f,
    0.33791524171829224f, 0.44070982933044434f, 0.5626170039176941f,
    0.7229568362236023f, 1.0f };

__device__ float g_w[(size_t)OUT_DIM * IN_DIM];   // folded weight, tf32-rounded
__device__ float g_x[(size_t)M_MAX * IN_DIM];     // tf32-rounded activations

__device__ __forceinline__ unsigned tf32_rna(float x) {
    unsigned u;
    asm("cvt.rna.tf32.f32 %0, %1;" : "=r"(u) : "f"(x));
    return u;
}

// ---------------------------------------------------------------------------
// Kernel 1: round X to tf32 (zero-mean rounding; kills MMA truncation bias)
// ---------------------------------------------------------------------------
__global__ void round_x_kernel(const float* __restrict__ x, float* __restrict__ xr, int n4) {
    int i = blockIdx.x * blockDim.x + threadIdx.x;
    if (i >= n4) return;
    float4 v = reinterpret_cast<const float4*>(x)[i];
    uint4 u;
    u.x = tf32_rna(v.x); u.y = tf32_rna(v.y);
    u.z = tf32_rna(v.z); u.w = tf32_rna(v.w);
    reinterpret_cast<uint4*>(xr)[i] = u;
}

// ---------------------------------------------------------------------------
// Kernel 2: W'[o,i] = nf4[wq]*scale + 2 * (B@A)[o,i]; tf32-rounded
// ---------------------------------------------------------------------------
__global__ void dequant_fold_kernel(const int* __restrict__ wq,
                                    const float* __restrict__ scales,
                                    const float* __restrict__ la,
                                    const float* __restrict__ lb,
                                    float* __restrict__ W) {
    __shared__ float cb[16];
    if (threadIdx.x < 16) cb[threadIdx.x] = c_nf4[threadIdx.x];
    __syncthreads();

    int idx = blockIdx.x * blockDim.x + threadIdx.x;
    const int n4 = OUT_DIM * (IN_DIM / 4);
    if (idx >= n4) return;
    int o  = idx >> 10;
    int i4 = idx & 1023;

    int4 c = reinterpret_cast<const int4*>(wq)[idx];
    float s = scales[o * (IN_DIM / 64) + (i4 >> 4)];

    float lx = 0.f, ly = 0.f, lz = 0.f, lw = 0.f;
    #pragma unroll
    for (int r = 0; r < RANK_; r++) {
        float bb = __ldg(&lb[o * RANK_ + r]);
        float4 av = reinterpret_cast<const float4*>(la)[r * (IN_DIM / 4) + i4];
        lx = fmaf(bb, av.x, lx); ly = fmaf(bb, av.y, ly);
        lz = fmaf(bb, av.z, lz); lw = fmaf(bb, av.w, lw);
    }

    float4 wv;
    wv.x = fmaf(cb[c.x], s, 2.0f * lx);
    wv.y = fmaf(cb[c.y], s, 2.0f * ly);
    wv.z = fmaf(cb[c.z], s, 2.0f * lz);
    wv.w = fmaf(cb[c.w], s, 2.0f * lw);

    uint4 u;
    u.x = tf32_rna(wv.x); u.y = tf32_rna(wv.y);
    u.z = tf32_rna(wv.z); u.w = tf32_rna(wv.w);
    reinterpret_cast<uint4*>(W)[idx] = u;
}

// ---------------------------------------------------------------------------
// Kernel 3: tf32 GEMM  C[M,N] = A[M,K] @ B[N,K]^T (both K-major, fp32 accum)
// CTA tile 128(M) x 256(N) x 32(K); 8 warps as 2(M) x 4(N), warp tile 64x64.
// 3-stage cp.async pipeline, one __syncthreads per k-tile.
// ---------------------------------------------------------------------------
#define BM 128
#define BN 256
#define BK 32
#define LDS_W  36          // BK + 4 pad floats (16B-aligned, conflict-free)
#define STAGES 3
#define A_ST  (BM * LDS_W) // floats per A stage
#define B_ST  (BN * LDS_W) // floats per B stage

__device__ __forceinline__ unsigned smem_u32(const void* p) {
    return (unsigned)__cvta_generic_to_shared(p);
}

__global__ void __launch_bounds__(256, 1)
gemm_tf32_kernel(const float* __restrict__ A, const float* __restrict__ B,
                 float* __restrict__ C, int M, int N, int K) {
    extern __shared__ float sm[];
    float* As = sm;                       // STAGES * A_ST
    float* Bs = sm + STAGES * A_ST;       // STAGES * B_ST

    const int tid  = threadIdx.x;
    const int lane = tid & 31;
    const int w    = tid >> 5;
    const int wm   = (w & 1) * 64;        // warp tile: 64(M) x 64(N)
    const int wn   = (w >> 1) * 64;
    const int g    = lane >> 2;           // groupID (row within 8)
    const int tg   = lane & 3;            // thread in group (col pair)

    // 64 consecutive CTAs share one N-tile (B stays L2-resident per wave)
    const int mtile = blockIdx.x & 63;            // 64 M-tiles
    const int ntile = blockIdx.x >> 6;            // 16 N-tiles

    const int lrow = tid >> 3;            // 0..31
    const int lcol = (tid & 7) * 4;       // 0..28 step 4

    const float* Ag = A + (size_t)(mtile * BM + lrow) * K + lcol;
    const float* Bg = B + (size_t)(ntile * BN + lrow) * K + lcol;

    float acc[4][8][4];
    #pragma unroll
    for (int a = 0; a < 4; a++)
        #pragma unroll
        for (int b = 0; b < 8; b++)
            #pragma unroll
            for (int c = 0; c < 4; c++) acc[a][b][c] = 0.f;

    const int KT = K / BK;   // 128

    auto load_stage = [&](int buf, int kt) {
        unsigned abase = smem_u32(As + buf * A_ST);
        unsigned bbase = smem_u32(Bs + buf * B_ST);
        const float* asrc = Ag + (size_t)kt * BK;
        const float* bsrc = Bg + (size_t)kt * BK;
        #pragma unroll
        for (int p = 0; p < 4; p++) {   // A: 128 rows
            unsigned ad = abase + (unsigned)(((lrow + p * 32) * LDS_W + lcol) * 4);
            asm volatile("cp.async.cg.shared.global [%0], [%1], 16;\n"
                         :: "r"(ad), "l"(asrc + (size_t)p * 32 * K));
        }
        #pragma unroll
        for (int p = 0; p < 8; p++) {   // B: 256 rows
            unsigned bd = bbase + (unsigned)(((lrow + p * 32) * LDS_W + lcol) * 4);
            asm volatile("cp.async.cg.shared.global [%0], [%1], 16;\n"
                         :: "r"(bd), "l"(bsrc + (size_t)p * 32 * K));
        }
    };

    load_stage(0, 0);
    asm volatile("cp.async.commit_group;\n");
    load_stage(1, 1);
    asm volatile("cp.async.commit_group;\n");

    int buf = 0;
    for (int kt = 0; kt < KT; kt++) {
        // stage kt resident; stage kt+1 may still be in flight
        asm volatile("cp.async.wait_group 1;\n");
        __syncthreads();   // data visible to all warps; prev compute finished

        // prefetch stage kt+2 into the buffer freed by compute kt-1
        if (kt + 2 < KT) load_stage((buf + 2) % STAGES, kt + 2);
        asm volatile("cp.async.commit_group;\n");

        const float* as = As + buf * A_ST;
        const float* bs = Bs + buf * B_ST;

        #pragma unroll
        for (int s = 0; s < 4; s++) {    // four k=8 slices
            unsigned af[4][4], bf[8][2];
            #pragma unroll
            for (int mi = 0; mi < 4; mi++) {
                const float* p = as + (wm + mi * 16 + g) * LDS_W + s * 8 + tg;
                af[mi][0] = __float_as_uint(p[0]);
                af[mi][1] = __float_as_uint(p[8 * LDS_W]);
                af[mi][2] = __float_as_uint(p[4]);
                af[mi][3] = __float_as_uint(p[8 * LDS_W + 4]);
            }
            #pragma unroll
            for (int ni = 0; ni < 8; ni++) {
                const float* p = bs + (wn + ni * 8 + g) * LDS_W + s * 8 + tg;
                bf[ni][0] = __float_as_uint(p[0]);
                bf[ni][1] = __float_as_uint(p[4]);
            }
            #pragma unroll
            for (int mi = 0; mi < 4; mi++)
                #pragma unroll
                for (int ni = 0; ni < 8; ni++) {
                    asm volatile(
                        "mma.sync.aligned.m16n8k8.row.col.f32.tf32.tf32.f32 "
                        "{%0,%1,%2,%3}, {%4,%5,%6,%7}, {%8,%9}, {%0,%1,%2,%3};\n"
                        : "+f"(acc[mi][ni][0]), "+f"(acc[mi][ni][1]),
                          "+f"(acc[mi][ni][2]), "+f"(acc[mi][ni][3])
                        : "r"(af[mi][0]), "r"(af[mi][1]), "r"(af[mi][2]), "r"(af[mi][3]),
                          "r"(bf[ni][0]), "r"(bf[ni][1]));
                }
        }
        buf = (buf + 1) % STAGES;
    }

    // epilogue: direct fp32 stores
    #pragma unroll
    for (int mi = 0; mi < 4; mi++) {
        int row0 = mtile * BM + wm + mi * 16 + g;
        #pragma unroll
        for (int ni = 0; ni < 8; ni++) {
            int col = ntile * BN + wn + ni * 8 + tg * 2;
            float2 v0 = make_float2(acc[mi][ni][0], acc[mi][ni][1]);
            float2 v1 = make_float2(acc[mi][ni][2], acc[mi][ni][3]);
            *reinterpret_cast<float2*>(&C[(size_t)row0 * N + col])       = v0;
            *reinterpret_cast<float2*>(&C[(size_t)(row0 + 8) * N + col]) = v1;
        }
    }
}

// ---------------------------------------------------------------------------
// Launcher
// ---------------------------------------------------------------------------
extern "C" void kernel_launch(void* const* d_in, const int* in_sizes, int n_in,
                              void* d_out, int out_size) {
    const float* x      = (const float*)d_in[0];
    const int*   wq     = (const int*)  d_in[1];
    const float* scales = (const float*)d_in[2];
    const float* la     = (const float*)d_in[3];
    const float* lb     = (const float*)d_in[4];
    float* out = (float*)d_out;

    int M = in_sizes[0] / IN_DIM;    // 8192

    float *gw = nullptr, *gx = nullptr;
    cudaGetSymbolAddress((void**)&gw, g_w);
    cudaGetSymbolAddress((void**)&gx, g_x);

    // 1) tf32-round X
    int n4x = (M * IN_DIM) / 4;
    round_x_kernel<<<(n4x + 255) / 256, 256>>>(x, gx, n4x);

    // 2) dequant + LoRA fold into W'
    int n4w = OUT_DIM * (IN_DIM / 4);
    dequant_fold_kernel<<<(n4w + 255) / 256, 256>>>(wq, scales, la, lb, gw);

    // 3) GEMM
    const int smem_bytes = STAGES * (A_ST + B_ST) * (int)sizeof(float); // 165888
    cudaFuncSetAttribute(gemm_tf32_kernel,
                         cudaFuncAttributeMaxDynamicSharedMemorySize, smem_bytes);
    int grid = (M / BM) * (OUT_DIM / BN);   // 64 * 16 = 1024
    gemm_tf32_kernel<<<grid, 256, smem_bytes>>>(gx, gw, out, M, OUT_DIM, IN_DIM);
}

// round 4
// speedup vs baseline: 1.7708x; 1.7156x over previous
#include <cuda_runtime.h>
#include <cuda_fp16.h>
#include <cstdint>
#include <cstddef>

// ---------------------------------------------------------------------------
// LoRALinear: fold NF4-dequant + LoRA into W' (fp16, RN), round X to fp16,
// then an fp16 mma.sync m16n8k16 GEMM (M=8192,N=4096,K=4096) with fp32 accum.
// fp16-RN operand rounding == tf32-rna mantissa budget (2^-11, zero-mean),
// so rel_err stays ~3e-4. Legacy tf32 HMMA was the pipe ceiling (~170 TF/s);
// k16 halves instruction count for the same MACs.
// ---------------------------------------------------------------------------

#define IN_DIM   4096
#define OUT_DIM  4096
#define RANK_    16
#define M_MAX    8192

__constant__ float c_nf4[16] = {
    -1.0f, -0.6961928009986877f, -0.5250730514526367f, -0.39491748809814453f,
    -0.28444138169288635f, -0.18477343022823334f, -0.09105003625154495f, 0.0f,
    0.07958029955625534f, 0.16093020141124725f, 0.24611230194568634f,
    0.33791524171829224f, 0.44070982933044434f, 0.5626170039176941f,
    0.7229568362236023f, 1.0f };

__device__ __half g_w[(size_t)OUT_DIM * IN_DIM];   // folded weight, fp16
__device__ __half g_x[(size_t)M_MAX * IN_DIM];     // rounded activations, fp16

// ---------------------------------------------------------------------------
// Kernel 1: X -> fp16 (RN). 8 elems/thread.
// ---------------------------------------------------------------------------
__global__ void round_x_kernel(const float* __restrict__ x, __half* __restrict__ xr, int n8) {
    int i = blockIdx.x * blockDim.x + threadIdx.x;
    if (i >= n8) return;
    float4 v0 = reinterpret_cast<const float4*>(x)[2 * i];
    float4 v1 = reinterpret_cast<const float4*>(x)[2 * i + 1];
    __half2 h[4];
    h[0] = __floats2half2_rn(v0.x, v0.y);
    h[1] = __floats2half2_rn(v0.z, v0.w);
    h[2] = __floats2half2_rn(v1.x, v1.y);
    h[3] = __floats2half2_rn(v1.z, v1.w);
    reinterpret_cast<uint4*>(xr)[i] = *reinterpret_cast<uint4*>(h);
}

// ---------------------------------------------------------------------------
// Kernel 2: W'[o,i] = nf4[wq]*scale + 2*(B@A)[o,i]  -> fp16 (RN)
// ---------------------------------------------------------------------------
__global__ void dequant_fold_kernel(const int* __restrict__ wq,
                                    const float* __restrict__ scales,
                                    const float* __restrict__ la,
                                    const float* __restrict__ lb,
                                    __half* __restrict__ W) {
    __shared__ float cb[16];
    if (threadIdx.x < 16) cb[threadIdx.x] = c_nf4[threadIdx.x];
    __syncthreads();

    int idx = blockIdx.x * blockDim.x + threadIdx.x;
    const int n4 = OUT_DIM * (IN_DIM / 4);
    if (idx >= n4) return;
    int o  = idx >> 10;
    int i4 = idx & 1023;

    int4 c = reinterpret_cast<const int4*>(wq)[idx];
    float s = scales[o * (IN_DIM / 64) + (i4 >> 4)];

    float lx = 0.f, ly = 0.f, lz = 0.f, lw = 0.f;
    #pragma unroll
    for (int r = 0; r < RANK_; r++) {
        float bb = __ldg(&lb[o * RANK_ + r]);
        float4 av = reinterpret_cast<const float4*>(la)[r * (IN_DIM / 4) + i4];
        lx = fmaf(bb, av.x, lx); ly = fmaf(bb, av.y, ly);
        lz = fmaf(bb, av.z, lz); lw = fmaf(bb, av.w, lw);
    }

    __half2 h0 = __floats2half2_rn(fmaf(cb[c.x], s, 2.0f * lx),
                                   fmaf(cb[c.y], s, 2.0f * ly));
    __half2 h1 = __floats2half2_rn(fmaf(cb[c.z], s, 2.0f * lz),
                                   fmaf(cb[c.w], s, 2.0f * lw));
    uint2 u = make_uint2(*reinterpret_cast<uint32_t*>(&h0),
                         *reinterpret_cast<uint32_t*>(&h1));
    reinterpret_cast<uint2*>(W)[idx] = u;
}

// ---------------------------------------------------------------------------
// Kernel 3: fp16 GEMM  C[M,N] = A[M,K] @ B[N,K]^T, fp32 accum.
// CTA 128x256x32, 8 warps 2(M)x4(N), warp tile 64x64.
// 4-stage cp.async, ldmatrix operand loads, one syncthreads per k-tile.
// ---------------------------------------------------------------------------
#define BM 128
#define BN 256
#define BK 32
#define LDS_H  40          // halves per smem row: 32 + 8 pad (80B, conflict-free)
#define STAGES 4
#define A_ST  (BM * LDS_H) // halves per A stage
#define B_ST  (BN * LDS_H)

__device__ __forceinline__ unsigned smem_u32(const void* p) {
    return (unsigned)__cvta_generic_to_shared(p);
}

__global__ void __launch_bounds__(256, 1)
gemm_fp16_kernel(const __half* __restrict__ A, const __half* __restrict__ B,
                 float* __restrict__ C, int M, int N, int K) {
    extern __shared__ __half sm[];
    __half* As = sm;                        // STAGES * A_ST
    __half* Bs = sm + STAGES * A_ST;        // STAGES * B_ST

    const int tid  = threadIdx.x;
    const int lane = tid & 31;
    const int w    = tid >> 5;
    const int wm   = (w & 1) * 64;          // warp tile 64(M) x 64(N)
    const int wn   = (w >> 1) * 64;
    const int g    = lane >> 2;
    const int tg   = lane & 3;

    // 64 consecutive CTAs share one N-tile (B L2-resident per wave)
    const int mtile = blockIdx.x & 63;
    const int ntile = blockIdx.x >> 6;

    // ldmatrix lane -> row/col-half decomposition
    const int a_row_off = (lane & 7) + ((lane >> 3) & 1) * 8;   // 0..15
    const int a_khalf   = (lane >> 4);                          // 0/1
    const int b_row_off = ((lane >> 4) & 1) * 8 + (lane & 7);   // 0..15
    const int b_khalf   = (lane >> 3) & 1;                      // 0/1

    float acc[4][8][4];
    #pragma unroll
    for (int a = 0; a < 4; a++)
        #pragma unroll
        for (int b = 0; b < 8; b++)
            #pragma unroll
            for (int c = 0; c < 4; c++) acc[a][b][c] = 0.f;

    const int KT = K / BK;   // 128

    const __half* Abase = A + (size_t)(mtile * BM) * K;
    const __half* Bbase = B + (size_t)(ntile * BN) * K;

    auto load_stage = [&](int buf, int kt) {
        unsigned abase = smem_u32(As + (size_t)buf * A_ST);
        unsigned bbase = smem_u32(Bs + (size_t)buf * B_ST);
        // A: 128 rows x 4 chunks of 16B
        #pragma unroll
        for (int p = 0; p < 2; p++) {
            int cid = p * 256 + tid;
            int r = cid >> 2, c = cid & 3;
            unsigned dst = abase + (unsigned)((r * LDS_H + c * 8) * 2);
            const __half* src = Abase + (size_t)r * K + kt * BK + c * 8;
            asm volatile("cp.async.cg.shared.global [%0], [%1], 16;\n"
                         :: "r"(dst), "l"(src));
        }
        // B: 256 rows x 4 chunks
        #pragma unroll
        for (int p = 0; p < 4; p++) {
            int cid = p * 256 + tid;
            int r = cid >> 2, c = cid & 3;
            unsigned dst = bbase + (unsigned)((r * LDS_H + c * 8) * 2);
            const __half* src = Bbase + (size_t)r * K + kt * BK + c * 8;
            asm volatile("cp.async.cg.shared.global [%0], [%1], 16;\n"
                         :: "r"(dst), "l"(src));
        }
    };

    load_stage(0, 0);
    asm volatile("cp.async.commit_group;\n");
    load_stage(1, 1);
    asm volatile("cp.async.commit_group;\n");
    load_stage(2, 2);
    asm volatile("cp.async.commit_group;\n");

    int buf = 0;
    for (int kt = 0; kt < KT; kt++) {
        asm volatile("cp.async.wait_group 2;\n");
        __syncthreads();

        if (kt + 3 < KT) load_stage((buf + 3) & 3, kt + 3);
        asm volatile("cp.async.commit_group;\n");

        unsigned abuf = smem_u32(As + (size_t)buf * A_ST);
        unsigned bbuf = smem_u32(Bs + (size_t)buf * B_ST);

        #pragma unroll
        for (int ks = 0; ks < 2; ks++) {     // two k=16 slices
            uint32_t af[4][4], bf[4][4];
            #pragma unroll
            for (int mi = 0; mi < 4; mi++) {
                unsigned addr = abuf + (unsigned)(((wm + mi * 16 + a_row_off) * LDS_H
                                                  + ks * 16 + a_khalf * 8) * 2);
                asm volatile("ldmatrix.sync.aligned.m8n8.x4.shared.b16 "
                             "{%0,%1,%2,%3}, [%4];"
                             : "=r"(af[mi][0]), "=r"(af[mi][1]),
                               "=r"(af[mi][2]), "=r"(af[mi][3]) : "r"(addr));
            }
            #pragma unroll
            for (int np = 0; np < 4; np++) {
                unsigned addr = bbuf + (unsigned)(((wn + np * 16 + b_row_off) * LDS_H
                                                  + ks * 16 + b_khalf * 8) * 2);
                asm volatile("ldmatrix.sync.aligned.m8n8.x4.shared.b16 "
                             "{%0,%1,%2,%3}, [%4];"
                             : "=r"(bf[np][0]), "=r"(bf[np][1]),
                               "=r"(bf[np][2]), "=r"(bf[np][3]) : "r"(addr));
            }
            #pragma unroll
            for (int mi = 0; mi < 4; mi++)
                #pragma unroll
                for (int np = 0; np < 4; np++) {
                    asm volatile(
                        "mma.sync.aligned.m16n8k16.row.col.f32.f16.f16.f32 "
                        "{%0,%1,%2,%3}, {%4,%5,%6,%7}, {%8,%9}, {%0,%1,%2,%3};\n"
                        : "+f"(acc[mi][2*np][0]), "+f"(acc[mi][2*np][1]),
                          "+f"(acc[mi][2*np][2]), "+f"(acc[mi][2*np][3])
                        : "r"(af[mi][0]), "r"(af[mi][1]), "r"(af[mi][2]), "r"(af[mi][3]),
                          "r"(bf[np][0]), "r"(bf[np][1]));
                    asm volatile(
                        "mma.sync.aligned.m16n8k16.row.col.f32.f16.f16.f32 "
                        "{%0,%1,%2,%3}, {%4,%5,%6,%7}, {%8,%9}, {%0,%1,%2,%3};\n"
                        : "+f"(acc[mi][2*np+1][0]), "+f"(acc[mi][2*np+1][1]),
                          "+f"(acc[mi][2*np+1][2]), "+f"(acc[mi][2*np+1][3])
                        : "r"(af[mi][0]), "r"(af[mi][1]), "r"(af[mi][2]), "r"(af[mi][3]),
                          "r"(bf[np][2]), "r"(bf[np][3]));
                }
        }
        buf = (buf + 1) & 3;
    }

    // epilogue: fp32 stores
    #pragma unroll
    for (int mi = 0; mi < 4; mi++) {
        int row0 = mtile * BM + wm + mi * 16 + g;
        #pragma unroll
        for (int ni = 0; ni < 8; ni++) {
            int col = ntile * BN + wn + ni * 8 + tg * 2;
            float2 v0 = make_float2(acc[mi][ni][0], acc[mi][ni][1]);
            float2 v1 = make_float2(acc[mi][ni][2], acc[mi][ni][3]);
            *reinterpret_cast<float2*>(&C[(size_t)row0 * N + col])       = v0;
            *reinterpret_cast<float2*>(&C[(size_t)(row0 + 8) * N + col]) = v1;
        }
    }
}

// ---------------------------------------------------------------------------
// Launcher
// ---------------------------------------------------------------------------
extern "C" void kernel_launch(void* const* d_in, const int* in_sizes, int n_in,
                              void* d_out, int out_size) {
    const float* x      = (const float*)d_in[0];
    const int*   wq     = (const int*)  d_in[1];
    const float* scales = (const float*)d_in[2];
    const float* la     = (const float*)d_in[3];
    const float* lb     = (const float*)d_in[4];
    float* out = (float*)d_out;

    int M = in_sizes[0] / IN_DIM;    // 8192

    __half *gw = nullptr, *gx = nullptr;
    cudaGetSymbolAddress((void**)&gw, g_w);
    cudaGetSymbolAddress((void**)&gx, g_x);

    // 1) X -> fp16
    int n8x = (M * IN_DIM) / 8;
    round_x_kernel<<<(n8x + 255) / 256, 256>>>(x, gx, n8x);

    // 2) dequant + LoRA fold -> fp16
    int n4w = OUT_DIM * (IN_DIM / 4);
    dequant_fold_kernel<<<(n4w + 255) / 256, 256>>>(wq, scales, la, lb, gw);

    // 3) GEMM
    const int smem_bytes = STAGES * (A_ST + B_ST) * (int)sizeof(__half); // 122880
    cudaFuncSetAttribute(gemm_fp16_kernel,
                         cudaFuncAttributeMaxDynamicSharedMemorySize, smem_bytes);
    int grid = (M / BM) * (OUT_DIM / BN);   // 1024
    gemm_fp16_kernel<<<grid, 256, smem_bytes>>>(gx, gw, out, M, OUT_DIM, IN_DIM);
}

// round 5
// speedup vs baseline: 1.9026x; 1.0744x over previous
#include <cuda_runtime.h>
#include <cuda_fp16.h>
#include <cstdint>
#include <cstddef>

// ---------------------------------------------------------------------------
// LoRALinear: fold NF4-dequant + LoRA into W' (fp16 RN), X -> fp16 RN, then
// fp16 m16n8k16 GEMM (M=8192,N=4096,K=4096), fp32 accum.
// R5 experiment: CTA tile 128x128, warp tile 64x32, __launch_bounds__(256,2)
// => 2 CTAs/SM, 4 warps/SMSP (vs 2 before). Tests latency- vs pipe-bound.
// ---------------------------------------------------------------------------

#define IN_DIM   4096
#define OUT_DIM  4096
#define RANK_    16
#define M_MAX    8192

__constant__ float c_nf4[16] = {
    -1.0f, -0.6961928009986877f, -0.5250730514526367f, -0.39491748809814453f,
    -0.28444138169288635f, -0.18477343022823334f, -0.09105003625154495f, 0.0f,
    0.07958029955625534f, 0.16093020141124725f, 0.24611230194568634f,
    0.33791524171829224f, 0.44070982933044434f, 0.5626170039176941f,
    0.7229568362236023f, 1.0f };

__device__ __half g_w[(size_t)OUT_DIM * IN_DIM];
__device__ __half g_x[(size_t)M_MAX * IN_DIM];

// ---------------------------------------------------------------------------
// Kernel 1: X -> fp16 (RN)
// ---------------------------------------------------------------------------
__global__ void round_x_kernel(const float* __restrict__ x, __half* __restrict__ xr, int n8) {
    int i = blockIdx.x * blockDim.x + threadIdx.x;
    if (i >= n8) return;
    float4 v0 = reinterpret_cast<const float4*>(x)[2 * i];
    float4 v1 = reinterpret_cast<const float4*>(x)[2 * i + 1];
    __half2 h[4];
    h[0] = __floats2half2_rn(v0.x, v0.y);
    h[1] = __floats2half2_rn(v0.z, v0.w);
    h[2] = __floats2half2_rn(v1.x, v1.y);
    h[3] = __floats2half2_rn(v1.z, v1.w);
    reinterpret_cast<uint4*>(xr)[i] = *reinterpret_cast<uint4*>(h);
}

// ---------------------------------------------------------------------------
// Kernel 2: W'[o,i] = nf4[wq]*scale + 2*(B@A)[o,i]  -> fp16 (RN)
// ---------------------------------------------------------------------------
__global__ void dequant_fold_kernel(const int* __restrict__ wq,
                                    const float* __restrict__ scales,
                                    const float* __restrict__ la,
                                    const float* __restrict__ lb,
                                    __half* __restrict__ W) {
    __shared__ float cb[16];
    if (threadIdx.x < 16) cb[threadIdx.x] = c_nf4[threadIdx.x];
    __syncthreads();

    int idx = blockIdx.x * blockDim.x + threadIdx.x;
    const int n4 = OUT_DIM * (IN_DIM / 4);
    if (idx >= n4) return;
    int o  = idx >> 10;
    int i4 = idx & 1023;

    int4 c = reinterpret_cast<const int4*>(wq)[idx];
    float s = scales[o * (IN_DIM / 64) + (i4 >> 4)];

    float lx = 0.f, ly = 0.f, lz = 0.f, lw = 0.f;
    #pragma unroll
    for (int r = 0; r < RANK_; r++) {
        float bb = __ldg(&lb[o * RANK_ + r]);
        float4 av = reinterpret_cast<const float4*>(la)[r * (IN_DIM / 4) + i4];
        lx = fmaf(bb, av.x, lx); ly = fmaf(bb, av.y, ly);
        lz = fmaf(bb, av.z, lz); lw = fmaf(bb, av.w, lw);
    }

    __half2 h0 = __floats2half2_rn(fmaf(cb[c.x], s, 2.0f * lx),
                                   fmaf(cb[c.y], s, 2.0f * ly));
    __half2 h1 = __floats2half2_rn(fmaf(cb[c.z], s, 2.0f * lz),
                                   fmaf(cb[c.w], s, 2.0f * lw));
    uint2 u = make_uint2(*reinterpret_cast<uint32_t*>(&h0),
                         *reinterpret_cast<uint32_t*>(&h1));
    reinterpret_cast<uint2*>(W)[idx] = u;
}

// ---------------------------------------------------------------------------
// Kernel 3: fp16 GEMM, CTA 128x128x32, 8 warps 2(M)x4(N), warp tile 64x32.
// 4-stage cp.async, 2 CTAs/SM.
// ---------------------------------------------------------------------------
#define BM 128
#define BN 128
#define BK 32
#define LDS_H  40          // halves per row: 32 + 8 pad
#define STAGES 4
#define A_ST  (BM * LDS_H)
#define B_ST  (BN * LDS_H)

__device__ __forceinline__ unsigned smem_u32(const void* p) {
    return (unsigned)__cvta_generic_to_shared(p);
}

__global__ void __launch_bounds__(256, 2)
gemm_fp16_kernel(const __half* __restrict__ A, const __half* __restrict__ B,
                 float* __restrict__ C, int M, int N, int K) {
    extern __shared__ __half sm[];
    __half* As = sm;
    __half* Bs = sm + STAGES * A_ST;

    const int tid  = threadIdx.x;
    const int lane = tid & 31;
    const int w    = tid >> 5;
    const int wm   = (w & 1) * 64;          // warp tile 64(M) x 32(N)
    const int wn   = (w >> 1) * 32;
    const int g    = lane >> 2;
    const int tg   = lane & 3;

    // 64 consecutive CTAs share one N-tile (B L2-resident per wave)
    const int mtile = blockIdx.x & 63;      // 64 M-tiles
    const int ntile = blockIdx.x >> 6;      // 32 N-tiles

    const int a_row_off = (lane & 7) + ((lane >> 3) & 1) * 8;
    const int a_khalf   = (lane >> 4);
    const int b_row_off = ((lane >> 4) & 1) * 8 + (lane & 7);
    const int b_khalf   = (lane >> 3) & 1;

    float acc[4][4][4];
    #pragma unroll
    for (int a = 0; a < 4; a++)
        #pragma unroll
        for (int b = 0; b < 4; b++)
            #pragma unroll
            for (int c = 0; c < 4; c++) acc[a][b][c] = 0.f;

    const int KT = K / BK;   // 128

    const __half* Abase = A + (size_t)(mtile * BM) * K;
    const __half* Bbase = B + (size_t)(ntile * BN) * K;

    auto load_stage = [&](int buf, int kt) {
        unsigned abase = smem_u32(As + (size_t)buf * A_ST);
        unsigned bbase = smem_u32(Bs + (size_t)buf * B_ST);
        #pragma unroll
        for (int p = 0; p < 2; p++) {       // A: 128 rows x 4 chunks
            int cid = p * 256 + tid;
            int r = cid >> 2, c = cid & 3;
            unsigned dst = abase + (unsigned)((r * LDS_H + c * 8) * 2);
            const __half* src = Abase + (size_t)r * K + kt * BK + c * 8;
            asm volatile("cp.async.cg.shared.global [%0], [%1], 16;\n"
                         :: "r"(dst), "l"(src));
        }
        #pragma unroll
        for (int p = 0; p < 2; p++) {       // B: 128 rows x 4 chunks
            int cid = p * 256 + tid;
            int r = cid >> 2, c = cid & 3;
            unsigned dst = bbase + (unsigned)((r * LDS_H + c * 8) * 2);
            const __half* src = Bbase + (size_t)r * K + kt * BK + c * 8;
            asm volatile("cp.async.cg.shared.global [%0], [%1], 16;\n"
                         :: "r"(dst), "l"(src));
        }
    };

    load_stage(0, 0);
    asm volatile("cp.async.commit_group;\n");
    load_stage(1, 1);
    asm volatile("cp.async.commit_group;\n");
    load_stage(2, 2);
    asm volatile("cp.async.commit_group;\n");

    int buf = 0;
    for (int kt = 0; kt < KT; kt++) {
        asm volatile("cp.async.wait_group 2;\n");
        __syncthreads();

        if (kt + 3 < KT) load_stage((buf + 3) & 3, kt + 3);
        asm volatile("cp.async.commit_group;\n");

        unsigned abuf = smem_u32(As + (size_t)buf * A_ST);
        unsigned bbuf = smem_u32(Bs + (size_t)buf * B_ST);

        #pragma unroll
        for (int ks = 0; ks < 2; ks++) {
            uint32_t af[4][4], bf[2][4];
            #pragma unroll
            for (int mi = 0; mi < 4; mi++) {
                unsigned addr = abuf + (unsigned)(((wm + mi * 16 + a_row_off) * LDS_H
                                                  + ks * 16 + a_khalf * 8) * 2);
                asm volatile("ldmatrix.sync.aligned.m8n8.x4.shared.b16 "
                             "{%0,%1,%2,%3}, [%4];"
                             : "=r"(af[mi][0]), "=r"(af[mi][1]),
                               "=r"(af[mi][2]), "=r"(af[mi][3]) : "r"(addr));
            }
            #pragma unroll
            for (int np = 0; np < 2; np++) {
                unsigned addr = bbuf + (unsigned)(((wn + np * 16 + b_row_off) * LDS_H
                                                  + ks * 16 + b_khalf * 8) * 2);
                asm volatile("ldmatrix.sync.aligned.m8n8.x4.shared.b16 "
                             "{%0,%1,%2,%3}, [%4];"
                             : "=r"(bf[np][0]), "=r"(bf[np][1]),
                               "=r"(bf[np][2]), "=r"(bf[np][3]) : "r"(addr));
            }
            #pragma unroll
            for (int mi = 0; mi < 4; mi++)
                #pragma unroll
                for (int np = 0; np < 2; np++) {
                    asm volatile(
                        "mma.sync.aligned.m16n8k16.row.col.f32.f16.f16.f32 "
                        "{%0,%1,%2,%3}, {%4,%5,%6,%7}, {%8,%9}, {%0,%1,%2,%3};\n"
                        : "+f"(acc[mi][2*np][0]), "+f"(acc[mi][2*np][1]),
                          "+f"(acc[mi][2*np][2]), "+f"(acc[mi][2*np][3])
                        : "r"(af[mi][0]), "r"(af[mi][1]), "r"(af[mi][2]), "r"(af[mi][3]),
                          "r"(bf[np][0]), "r"(bf[np][1]));
                    asm volatile(
                        "mma.sync.aligned.m16n8k16.row.col.f32.f16.f16.f32 "
                        "{%0,%1,%2,%3}, {%4,%5,%6,%7}, {%8,%9}, {%0,%1,%2,%3};\n"
                        : "+f"(acc[mi][2*np+1][0]), "+f"(acc[mi][2*np+1][1]),
                          "+f"(acc[mi][2*np+1][2]), "+f"(acc[mi][2*np+1][3])
                        : "r"(af[mi][0]), "r"(af[mi][1]), "r"(af[mi][2]), "r"(af[mi][3]),
                          "r"(bf[np][2]), "r"(bf[np][3]));
                }
        }
        buf = (buf + 1) & 3;
    }

    // epilogue
    #pragma unroll
    for (int mi = 0; mi < 4; mi++) {
        int row0 = mtile * BM + wm + mi * 16 + g;
        #pragma unroll
        for (int ni = 0; ni < 4; ni++) {
            int col = ntile * BN + wn + ni * 8 + tg * 2;
            float2 v0 = make_float2(acc[mi][ni][0], acc[mi][ni][1]);
            float2 v1 = make_float2(acc[mi][ni][2], acc[mi][ni][3]);
            *reinterpret_cast<float2*>(&C[(size_t)row0 * N + col])       = v0;
            *reinterpret_cast<float2*>(&C[(size_t)(row0 + 8) * N + col]) = v1;
        }
    }
}

// ---------------------------------------------------------------------------
// Launcher
// ---------------------------------------------------------------------------
extern "C" void kernel_launch(void* const* d_in, const int* in_sizes, int n_in,
                              void* d_out, int out_size) {
    const float* x      = (const float*)d_in[0];
    const int*   wq     = (const int*)  d_in[1];
    const float* scales = (const float*)d_in[2];
    const float* la     = (const float*)d_in[3];
    const float* lb     = (const float*)d_in[4];
    float* out = (float*)d_out;

    int M = in_sizes[0] / IN_DIM;    // 8192

    __half *gw = nullptr, *gx = nullptr;
    cudaGetSymbolAddress((void**)&gw, g_w);
    cudaGetSymbolAddress((void**)&gx, g_x);

    int n8x = (M * IN_DIM) / 8;
    round_x_kernel<<<(n8x + 255) / 256, 256>>>(x, gx, n8x);

    int n4w = OUT_DIM * (IN_DIM / 4);
    dequant_fold_kernel<<<(n4w + 255) / 256, 256>>>(wq, scales, la, lb, gw);

    const int smem_bytes = STAGES * (A_ST + B_ST) * (int)sizeof(__half); // 81920
    cudaFuncSetAttribute(gemm_fp16_kernel,
                         cudaFuncAttributeMaxDynamicSharedMemorySize, smem_bytes);
    int grid = (M / BM) * (OUT_DIM / BN);   // 64 * 32 = 2048
    gemm_fp16_kernel<<<grid, 256, smem_bytes>>>(gx, gw, out, M, OUT_DIM, IN_DIM);
}